// round 5
// baseline (speedup 1.0000x reference)
#include <cuda_runtime.h>
#include <cstdint>

// MeanAggregator: out[b, :] = mean_{s<S} features[neigh_idx[b,s], :]
// B=50000, S=10, N=1e6, D=128 (fp32).
//
// One warp per output row; each lane owns one float4 column (32*16B = 512B =
// one full feature row per LDG wave, fully coalesced). All 10 indices are
// preloaded as uint32 BYTE offsets (idx*512 < 2^32) so the gather loop is 10
// independent LDG.128 with MLP=10 and minimal register footprint.
//
// Index dtype (int32 vs int64) is detected inline: odd 32-bit words of the
// first 4 elements are all zero iff the buffer is little-endian int64 with
// values < 2^31. With random int32 indices in [0,1e6) the false-positive
// probability is ~1e-24. The 4 detection loads hit one cached sector shared
// by every warp.

#define AGG_B 50000
#define AGG_S 10
#define AGG_D 128
#define AGG_VEC (AGG_D / 4)   // 32 float4 per row == one per lane

__global__ __launch_bounds__(256, 8) void mean_agg_kernel(
    const unsigned* __restrict__ idx_raw,     // [B,S] int32 OR int64 words
    const char* __restrict__ features,        // [N, 512B rows]
    float4* __restrict__ out)                 // [B, 32] as float4
{
    const int gtid = blockIdx.x * blockDim.x + threadIdx.x;
    const int row  = gtid >> 5;          // warp id == output row
    const int lane = gtid & 31;          // lane == float4 column
    if (row >= AGG_B) return;

    // Inline dtype detection (one broadcast sector, L1-resident after warp 0)
    const unsigned w1 = __ldg(idx_raw + 1);
    const unsigned w3 = __ldg(idx_raw + 3);
    const unsigned w5 = __ldg(idx_raw + 5);
    const unsigned w7 = __ldg(idx_raw + 7);
    const bool is64 = ((w1 | w3 | w5 | w7) == 0u);

    // Preload all S indices as byte offsets (broadcast loads: 1 txn per row)
    unsigned off[AGG_S];
    if (is64) {
        const unsigned* nb = idx_raw + (size_t)row * AGG_S * 2;
#pragma unroll
        for (int s = 0; s < AGG_S; s++)
            off[s] = __ldg(nb + 2 * s) << 9;           // idx * 512
    } else {
        const unsigned* nb = idx_raw + row * AGG_S;
#pragma unroll
        for (int s = 0; s < AGG_S; s++)
            off[s] = __ldg(nb + s) << 9;               // idx * 512
    }

    const char* fb = features + lane * 16;   // hoisted lane offset

    float4 acc = make_float4(0.f, 0.f, 0.f, 0.f);
#pragma unroll
    for (int s = 0; s < AGG_S; s++) {
        float4 v = __ldg((const float4*)(fb + off[s]));
        acc.x += v.x; acc.y += v.y; acc.z += v.z; acc.w += v.w;
    }

    const float inv = 1.0f / (float)AGG_S;
    acc.x *= inv; acc.y *= inv; acc.z *= inv; acc.w *= inv;
    out[row * AGG_VEC + lane] = acc;
}

extern "C" void kernel_launch(void* const* d_in, const int* in_sizes, int n_in,
                              void* d_out, int out_size)
{
    const unsigned* neigh_idx = (const unsigned*)d_in[0];  // [B,S] i32/i64
    const char*     features  = (const char*)d_in[1];      // fp32 [N, D]
    float4*         out       = (float4*)d_out;            // fp32 [B, D]

    const int threads = 256;                       // 8 warps / block
    const int total_threads = AGG_B * 32;          // one warp per row
    const int blocks = (total_threads + threads - 1) / threads;
    mean_agg_kernel<<<blocks, threads>>>(neigh_idx, features, out);
}

// round 7
// speedup vs baseline: 1.2947x; 1.2947x over previous
#include <cuda_runtime.h>
#include <cstdint>

// MeanAggregator: out[b, :] = mean_{s<S} features[neigh_idx[b,s], :]
// B=50000, S=10, N=1e6, D=128 (fp32).
//
// One warp per output row; each lane owns one float4 column (32*16B = 512B =
// one full feature row per LDG wave, fully coalesced). All 10 indices are
// preloaded as uint32 BYTE offsets (idx*512 < 2^32) -> 10 independent
// LDG.128 (MLP=10) with minimal register footprint.
//
// L2 policy: output stores and index loads are streaming (evict-first) so the
// write-once 26MB output and read-once 2MB indices don't evict feature lines
// (features have ~1.27x average reuse across the batch). Matters in the timed
// replay loop where L2 is warm.
//
// Index dtype (int32 vs int64) detected inline: odd 32-bit words of the first
// 4 elements are all zero iff little-endian int64 with values < 2^31.

#define AGG_B 50000
#define AGG_S 10
#define AGG_D 128
#define AGG_VEC (AGG_D / 4)   // 32 float4 per row == one per lane

__global__ __launch_bounds__(256, 8) void mean_agg_kernel(
    const unsigned* __restrict__ idx_raw,     // [B,S] int32 OR int64 words
    const char* __restrict__ features,        // [N, 512B rows]
    float4* __restrict__ out)                 // [B, 32] as float4
{
    const int gtid = blockIdx.x * blockDim.x + threadIdx.x;
    const int row  = gtid >> 5;          // warp id == output row
    const int lane = gtid & 31;          // lane == float4 column
    if (row >= AGG_B) return;

    // Inline dtype detection (one broadcast sector, L1-resident after warp 0)
    const unsigned w1 = __ldg(idx_raw + 1);
    const unsigned w3 = __ldg(idx_raw + 3);
    const unsigned w5 = __ldg(idx_raw + 5);
    const unsigned w7 = __ldg(idx_raw + 7);
    const bool is64 = ((w1 | w3 | w5 | w7) == 0u);

    // Preload all S indices as byte offsets (broadcast + streaming loads)
    unsigned off[AGG_S];
    if (is64) {
        const unsigned* nb = idx_raw + (size_t)row * AGG_S * 2;
#pragma unroll
        for (int s = 0; s < AGG_S; s++)
            off[s] = __ldcs(nb + 2 * s) << 9;          // idx * 512
    } else {
        const unsigned* nb = idx_raw + row * AGG_S;
#pragma unroll
        for (int s = 0; s < AGG_S; s++)
            off[s] = __ldcs(nb + s) << 9;              // idx * 512
    }

    const char* fb = features + lane * 16;   // hoisted lane offset

    float4 acc = make_float4(0.f, 0.f, 0.f, 0.f);
#pragma unroll
    for (int s = 0; s < AGG_S; s++) {
        float4 v = __ldg((const float4*)(fb + off[s]));
        acc.x += v.x; acc.y += v.y; acc.z += v.z; acc.w += v.w;
    }

    const float inv = 1.0f / (float)AGG_S;
    acc.x *= inv; acc.y *= inv; acc.z *= inv; acc.w *= inv;

    // Streaming store: write-once output must not evict feature lines from L2
    __stcs(&out[row * AGG_VEC + lane], acc);
}

extern "C" void kernel_launch(void* const* d_in, const int* in_sizes, int n_in,
                              void* d_out, int out_size)
{
    const unsigned* neigh_idx = (const unsigned*)d_in[0];  // [B,S] i32/i64
    const char*     features  = (const char*)d_in[1];      // fp32 [N, D]
    float4*         out       = (float4*)d_out;            // fp32 [B, D]

    const int threads = 256;                       // 8 warps / block
    const int total_threads = AGG_B * 32;          // one warp per row
    const int blocks = (total_threads + threads - 1) / threads;
    mean_agg_kernel<<<blocks, threads>>>(neigh_idx, features, out);
}